// round 7
// baseline (speedup 1.0000x reference)
#include <cuda_runtime.h>
#include <cuda_bf16.h>

// x: (256,64,25,3) f32; W_conv: (3,192) f32; W_a: (128,1) f32; out: (256,3,25,25) f32
// Verified math (R1/R3):
//   xbar[j] = sum_t x[n,t,j], j=v*3+i (1/64 folded into u)
//   u{1,2}[i,k] = (1/64) sum_c W_conv[i,c*3+k]*W_a[{0,64}+c]
//   s{1,2}[v,k] = sum_i xbar[v*3+i]*u{1,2}[i,k]
//   row(0..74), col q: e = s1[(row%3)*25+q] + s2[(row/3)*3 + ((row%3)+q)%3]
//   E = leaky(e,0.2)=max(e,0.2e); softmax over q.
// R7 MUFU-kill: exp2(max(e,0.2e)) = max(exp2 e, exp2 0.2e)   [exp2 monotone]
//   and each branch factors: exp2(e)=E1[r]*E2[.], exp2(0.2e)=F1[r]*F2[.].
//   Precompute packed (E1,F1)/(E2,F2) per column (300 ex2/block);
//   per element: LDS.64 + mul.rn.f32x2 + FMNMX + FADD. No MUFU in hot loop.

#define TPB 320

__device__ __forceinline__ unsigned long long add2(unsigned long long a, unsigned long long b) {
    unsigned long long r;
    asm("add.rn.f32x2 %0, %1, %2;" : "=l"(r) : "l"(a), "l"(b));
    return r;
}
__device__ __forceinline__ unsigned long long mul2(unsigned long long a, unsigned long long b) {
    unsigned long long r;
    asm("mul.rn.f32x2 %0, %1, %2;" : "=l"(r) : "l"(a), "l"(b));
    return r;
}
__device__ __forceinline__ unsigned long long pack2(float lo, float hi) {
    unsigned long long r;
    asm("mov.b64 %0, {%1, %2};" : "=l"(r) : "f"(lo), "f"(hi));
    return r;
}
__device__ __forceinline__ void unpack2(unsigned long long v, float &lo, float &hi) {
    asm("mov.b64 {%0, %1}, %2;" : "=f"(lo), "=f"(hi) : "l"(v));
}
__device__ __forceinline__ float ex2a(float x) {
    float r; asm("ex2.approx.f32 %0, %1;" : "=f"(r) : "f"(x)); return r;
}

__global__ __launch_bounds__(TPB)
void gat_adj_kernel(const float* __restrict__ x,
                    const float* __restrict__ Wc,
                    const float* __restrict__ Wa,
                    float* __restrict__ out)
{
    __shared__ __align__(16) float buf[600];            // 8 partial slots x 75 cols
    __shared__ float uu[18];                            // [which*9+i*3+k], /64 folded
    __shared__ unsigned long long ep1[75], ep2[75];     // packed (E,F) per column

    const int n   = blockIdx.x;
    const int tid = threadIdx.x;

    // ---- Phase 1: 150 threads x 8 LDG.128 (front-batched MLP), reg tree-fold ----
    // float flat f = 4*(tid+150k)+m: col (4tid+m)%75 is k-invariant (600%75==0);
    // per-thread partial lands at slot (4tid+m)/75, i.e. buf[4tid+m].
    if (tid < 150) {
        const ulonglong2* xg = reinterpret_cast<const ulonglong2*>(x) + (size_t)n * 1200;
        ulonglong2 v0 = xg[tid];
        ulonglong2 v1 = xg[tid + 150];
        ulonglong2 v2 = xg[tid + 300];
        ulonglong2 v3 = xg[tid + 450];
        ulonglong2 v4 = xg[tid + 600];
        ulonglong2 v5 = xg[tid + 750];
        ulonglong2 v6 = xg[tid + 900];
        ulonglong2 v7 = xg[tid + 1050];
        ulonglong2 s;
        s.x = add2(add2(add2(v0.x, v1.x), add2(v2.x, v3.x)),
                   add2(add2(v4.x, v5.x), add2(v6.x, v7.x)));
        s.y = add2(add2(add2(v0.y, v1.y), add2(v2.y, v3.y)),
                   add2(add2(v4.y, v5.y), add2(v6.y, v7.y)));
        reinterpret_cast<ulonglong2*>(buf)[tid] = s;
    } else if (tid >= 160) {
        // ---- u matrices: 18 outputs x 8 lanes, shfl-reduced (hidden under x loads)
        int idx = tid - 160;
        const bool real = (idx < 144);
        if (idx > 143) idx = 143;
        const int o = idx >> 3, p = idx & 7;
        const int which = o / 9, rem = o % 9;
        const int i = rem / 3, k = rem % 3;
        const int c0 = p * 8;
        const float* wcb = Wc + i * 192 + k;
        const float4 wa0 = *reinterpret_cast<const float4*>(Wa + which * 64 + c0);
        const float4 wa1 = *reinterpret_cast<const float4*>(Wa + which * 64 + c0 + 4);
        float acc = wcb[(c0 + 0) * 3] * wa0.x + wcb[(c0 + 1) * 3] * wa0.y
                  + wcb[(c0 + 2) * 3] * wa0.z + wcb[(c0 + 3) * 3] * wa0.w
                  + wcb[(c0 + 4) * 3] * wa1.x + wcb[(c0 + 5) * 3] * wa1.y
                  + wcb[(c0 + 6) * 3] * wa1.z + wcb[(c0 + 7) * 3] * wa1.w;
        acc += __shfl_xor_sync(0xffffffffu, acc, 1);
        acc += __shfl_xor_sync(0xffffffffu, acc, 2);
        acc += __shfl_xor_sync(0xffffffffu, acc, 4);
        if (p == 0 && real) uu[o] = acc * (1.0f / 64.0f);
    }
    __syncthreads();   // bar 0

    // ---- Phase 2: fold + scores + precomputed exps (warps 0..2, col = w*30+lane) ----
    if (tid < 96) {
        const int w = tid >> 5, lane = tid & 31;
        const int col  = w * 30 + lane;
        const int colc = (col > 74) ? 74 : col;
        float xb = 0.f;
        #pragma unroll
        for (int i = 0; i < 8; i++) xb += buf[i * 75 + colc];

        const int k    = lane % 3;
        const int base = lane - k;
        const float a0 = __shfl_sync(0xffffffffu, xb, base);
        const float a1 = __shfl_sync(0xffffffffu, xb, base + 1);
        const float a2 = __shfl_sync(0xffffffffu, xb, base + 2);

        const float s1 = a0 * uu[k]     + a1 * uu[3 + k]  + a2 * uu[6 + k];
        const float s2 = a0 * uu[9 + k] + a1 * uu[12 + k] + a2 * uu[15 + k];
        const float L2E  = 1.4426950408889634f;
        const float L2E5 = 0.2f * L2E;
        const float E1 = ex2a(s1 * L2E),  F1 = ex2a(s1 * L2E5);
        const float E2 = ex2a(s2 * L2E),  F2 = ex2a(s2 * L2E5);
        if (lane < 30 && col < 75) {
            ep1[col] = pack2(E1, F1);
            ep2[col] = pack2(E2, F2);
        }
    }
    __syncthreads();   // bar 1

    // ---- Phase 3: softmax, 4 threads/row (verified R3 map), MUFU-free hot loop ----
    {
        int row = tid >> 2;
        if (row > 74) row = 74;                 // tid 300..319: safe duplicate work
        const int part = tid & 3;
        const int d  = row % 3;
        const int a3 = row - d;
        const int r0 = d * 25;

        const unsigned long long c0 = ep2[a3];
        const unsigned long long c1 = ep2[a3 + 1];
        const unsigned long long c2 = ep2[a3 + 2];

        const int qs  = (part == 0) ? 0 : part * 6 + 1;   // 0,7,13,19
        const int cnt = (part == 0) ? 7 : 6;

        const int kk0 = (d + qs) % 3;
        unsigned long long ra = (kk0 == 0) ? c0 : ((kk0 == 1) ? c1 : c2);
        unsigned long long rb = (kk0 == 0) ? c1 : ((kk0 == 1) ? c2 : c0);
        unsigned long long rc = (kk0 == 0) ? c2 : ((kk0 == 1) ? c0 : c1);

        float vals[7];
        float sum = 0.f;
        #pragma unroll
        for (int j = 0; j < 7; j++) {
            if (j < cnt) {
                const unsigned long long pr = mul2(ep1[r0 + qs + j], ra);
                float pe, pf;
                unpack2(pr, pe, pf);
                const float vl = fmaxf(pe, pf);   // = exp2(leaky(e)) by monotonicity
                vals[j] = vl;
                sum += vl;
                unsigned long long t = ra; ra = rb; rb = rc; rc = t;
            }
        }
        sum += __shfl_xor_sync(0xffffffffu, sum, 1);
        sum += __shfl_xor_sync(0xffffffffu, sum, 2);
        const float inv = __fdividef(1.0f, sum);

        if ((tid >> 2) < 75) {
            float* og = out + (size_t)n * 1875 + row * 25 + qs;
            #pragma unroll
            for (int j = 0; j < 7; j++)
                if (j < cnt) og[j] = vals[j] * inv;
        }
    }
}

extern "C" void kernel_launch(void* const* d_in, const int* in_sizes, int n_in,
                              void* d_out, int out_size)
{
    const float* x  = (const float*)d_in[0];
    const float* Wc = (const float*)d_in[1];
    const float* Wa = (const float*)d_in[2];
    float* out = (float*)d_out;
    gat_adj_kernel<<<256, TPB>>>(x, Wc, Wa, out);
}

// round 8
// speedup vs baseline: 1.0295x; 1.0295x over previous
#include <cuda_runtime.h>
#include <cuda_bf16.h>

// x: (256,64,25,3) f32; W_conv: (3,192) f32; W_a: (128,1) f32; out: (256,3,25,25) f32
// Verified math (R1/R3/R7):
//   xbar[j] = sum_t x[n,t,j], j=v*3+i (1/64 folded into u)
//   u{1,2}[i,k] = (1/64) sum_c W_conv[i,c*3+k]*W_a[{0,64}+c]
//   s{1,2}[v,k] = sum_i xbar[v*3+i]*u{1,2}[i,k]
//   row(0..74), col q: e = s1[(row%3)*25+q] + s2[(row/3)*3 + ((row%3)+q)%3]
//   exp(leaky(e)) = max(E1[r]*E2[c], F1[r]*F2[c]),  E=exp2(L2E*s), F=exp2(0.2*L2E*s)
//   (exp2 monotone => max commutes; each branch is separable. Verified R7, 9.6e-8.)
// R8 = R6 skeleton (300x4 loads + overlapped u) + 3-warp phase 2 + MUFU-free phase 3.

#define TPB 320

__device__ __forceinline__ unsigned long long add2(unsigned long long a, unsigned long long b) {
    unsigned long long r;
    asm("add.rn.f32x2 %0, %1, %2;" : "=l"(r) : "l"(a), "l"(b));
    return r;
}
__device__ __forceinline__ unsigned long long mul2(unsigned long long a, unsigned long long b) {
    unsigned long long r;
    asm("mul.rn.f32x2 %0, %1, %2;" : "=l"(r) : "l"(a), "l"(b));
    return r;
}
__device__ __forceinline__ unsigned long long pack2(float lo, float hi) {
    unsigned long long r;
    asm("mov.b64 %0, {%1, %2};" : "=l"(r) : "f"(lo), "f"(hi));
    return r;
}
__device__ __forceinline__ void unpack2(unsigned long long v, float &lo, float &hi) {
    asm("mov.b64 {%0, %1}, %2;" : "=f"(lo), "=f"(hi) : "l"(v));
}
__device__ __forceinline__ float ex2a(float x) {
    float r; asm("ex2.approx.f32 %0, %1;" : "=f"(r) : "f"(x)); return r;
}

__global__ __launch_bounds__(TPB)
void gat_adj_kernel(const float* __restrict__ x,
                    const float* __restrict__ Wc,
                    const float* __restrict__ Wa,
                    float* __restrict__ out)
{
    __shared__ __align__(16) float buf[1200];           // 16 partial slots x 75 cols
    __shared__ float uu[18];                            // [which*9+i*3+k], /64 folded
    __shared__ unsigned long long ep1[75], ep2[75];     // packed (E,F) per column

    const int n   = blockIdx.x;
    const int tid = threadIdx.x;

    // ---- Phase 1: 300 threads x 4 LDG.128 at t=0, reg tree-fold (R6, proven) ----
    ulonglong2 xa, xb, xc, xd;
    if (tid < 300) {
        const ulonglong2* xg = reinterpret_cast<const ulonglong2*>(x) + (size_t)n * 1200;
        xa = xg[tid];
        xb = xg[tid + 300];
        xc = xg[tid + 600];
        xd = xg[tid + 900];
    }

    // u inputs issued right behind x loads; compute hidden under x latency.
    float wc0, wc1, wc2, wc3;
    float4 wav;
    int o = 0;
    if (tid < 288) {
        o = tid >> 4;
        const int p     = tid & 15;
        const int which = o / 9;
        const int rem   = o % 9;
        const int i     = rem / 3;
        const int k     = rem % 3;
        const int c0    = 4 * p;
        const float* wcb = Wc + i * 192 + k;
        wc0 = wcb[(c0 + 0) * 3];
        wc1 = wcb[(c0 + 1) * 3];
        wc2 = wcb[(c0 + 2) * 3];
        wc3 = wcb[(c0 + 3) * 3];
        wav = reinterpret_cast<const float4*>(Wa + which * 64 + c0)[0];
    }
    if (tid < 288) {
        float acc = wc0 * wav.x + wc1 * wav.y + wc2 * wav.z + wc3 * wav.w;
        acc += __shfl_xor_sync(0xffffffffu, acc, 1);
        acc += __shfl_xor_sync(0xffffffffu, acc, 2);
        acc += __shfl_xor_sync(0xffffffffu, acc, 4);
        acc += __shfl_xor_sync(0xffffffffu, acc, 8);
        if ((tid & 15) == 0) uu[o] = acc * (1.0f / 64.0f);
    }

    if (tid < 300) {
        ulonglong2 s;
        s.x = add2(add2(xa.x, xb.x), add2(xc.x, xd.x));
        s.y = add2(add2(xa.y, xb.y), add2(xc.y, xd.y));
        reinterpret_cast<ulonglong2*>(buf)[tid] = s;   // buf[slot*75+col], col=(4tid+m)%75
    }
    __syncthreads();   // bar 0

    // ---- Phase 2: fold + scores + exps; 3 warps, col = w*27+lane (27%3==0 =>
    //      (v*3..v*3+2) triples stay inside one warp; neighbors via shfl) ----
    if (tid < 96) {
        const int w    = tid >> 5;
        const int lane = tid & 31;
        const int col  = w * 27 + lane;                // valid cols when lane<27 && col<75
        const bool on  = (lane < 27) && (col < 75);
        const int colc = on ? col : 74;

        float xv = 0.f;
        #pragma unroll
        for (int i = 0; i < 16; i++) xv += buf[i * 75 + colc];

        const int k    = lane % 3;                     // == col%3 when on (27w ≡ 0 mod 3)
        const int base = lane - k;
        const float a0 = __shfl_sync(0xffffffffu, xv, base);
        const float a1 = __shfl_sync(0xffffffffu, xv, base + 1);
        const float a2 = __shfl_sync(0xffffffffu, xv, base + 2);

        const float s1 = a0 * uu[k]     + a1 * uu[3 + k]  + a2 * uu[6 + k];
        const float s2 = a0 * uu[9 + k] + a1 * uu[12 + k] + a2 * uu[15 + k];
        const float L2E  = 1.4426950408889634f;
        const float L2E5 = 0.2f * L2E;
        const float E1 = ex2a(s1 * L2E),  F1 = ex2a(s1 * L2E5);
        const float E2 = ex2a(s2 * L2E),  F2 = ex2a(s2 * L2E5);
        if (on) {
            ep1[col] = pack2(E1, F1);
            ep2[col] = pack2(E2, F2);
        }
    }
    __syncthreads();   // bar 1

    // ---- Phase 3: softmax, 4 threads/row (verified map), MUFU-free hot loop ----
    {
        int row = tid >> 2;
        if (row > 74) row = 74;                 // tid 300..319: safe duplicate work
        const int part = tid & 3;
        const int d  = row % 3;
        const int a3 = row - d;
        const int r0 = d * 25;

        const unsigned long long c0 = ep2[a3];
        const unsigned long long c1 = ep2[a3 + 1];
        const unsigned long long c2 = ep2[a3 + 2];

        const int qs  = (part == 0) ? 0 : part * 6 + 1;   // 0,7,13,19
        const int cnt = (part == 0) ? 7 : 6;

        const int kk0 = (d + qs) % 3;
        unsigned long long ra = (kk0 == 0) ? c0 : ((kk0 == 1) ? c1 : c2);
        unsigned long long rb = (kk0 == 0) ? c1 : ((kk0 == 1) ? c2 : c0);
        unsigned long long rc = (kk0 == 0) ? c2 : ((kk0 == 1) ? c0 : c1);

        float vals[7];
        float sum = 0.f;
        #pragma unroll
        for (int j = 0; j < 7; j++) {
            if (j < cnt) {
                const unsigned long long pr = mul2(ep1[r0 + qs + j], ra);
                float pe, pf;
                unpack2(pr, pe, pf);
                const float vl = fmaxf(pe, pf);   // exp2(leaky(e)) by monotonicity
                vals[j] = vl;
                sum += vl;
                unsigned long long t = ra; ra = rb; rb = rc; rc = t;
            }
        }
        sum += __shfl_xor_sync(0xffffffffu, sum, 1);
        sum += __shfl_xor_sync(0xffffffffu, sum, 2);
        const float inv = __fdividef(1.0f, sum);

        if ((tid >> 2) < 75) {
            float* og = out + (size_t)n * 1875 + row * 25 + qs;
            #pragma unroll
            for (int j = 0; j < 7; j++)
                if (j < cnt) og[j] = vals[j] * inv;
        }
    }
}

extern "C" void kernel_launch(void* const* d_in, const int* in_sizes, int n_in,
                              void* d_out, int out_size)
{
    const float* x  = (const float*)d_in[0];
    const float* Wc = (const float*)d_in[1];
    const float* Wa = (const float*)d_in[2];
    float* out = (float*)d_out;
    gat_adj_kernel<<<256, TPB>>>(x, Wc, Wa, out);
}

// round 9
// speedup vs baseline: 1.0856x; 1.0545x over previous
#include <cuda_runtime.h>
#include <cuda_bf16.h>

// x: (256,64,25,3) f32; W_conv: (3,192) f32; W_a: (128,1) f32; out: (256,3,25,25) f32
// Verified math (R1/R3/R7):
//   xbar[j] = sum_t x[n,t,j], j=v*3+i (1/64 folded into u)
//   u{1,2}[i,k] = (1/64) sum_c W_conv[i,c*3+k]*W_a[{0,64}+c]
//   s{1,2}[v,k] = sum_i xbar[v*3+i]*u{1,2}[i,k]
//   row(0..74), col q: e = s1[(row%3)*25+q] + s2[(row/3)*3 + ((row%3)+q)%3]
//   exp(leaky(e)) = max(E1[r]*E2[c], F1[r]*F2[c]), E=exp2(L2E*s), F=exp2(0.2*L2E*s)
// R9: warp-specialization. Loader warps (tid<300) do ONLY x load+fold+STS;
//   u computed on dedicated lanes (tid 304..447, 18 outputs x 8 lanes x 8 terms,
//   masked shfl reduce) fully overlapped with x DRAM latency. bar0 arrival =
//   max(paths), not sum.

#define TPB 448

__device__ __forceinline__ unsigned long long add2(unsigned long long a, unsigned long long b) {
    unsigned long long r;
    asm("add.rn.f32x2 %0, %1, %2;" : "=l"(r) : "l"(a), "l"(b));
    return r;
}
__device__ __forceinline__ unsigned long long mul2(unsigned long long a, unsigned long long b) {
    unsigned long long r;
    asm("mul.rn.f32x2 %0, %1, %2;" : "=l"(r) : "l"(a), "l"(b));
    return r;
}
__device__ __forceinline__ unsigned long long pack2(float lo, float hi) {
    unsigned long long r;
    asm("mov.b64 %0, {%1, %2};" : "=l"(r) : "f"(lo), "f"(hi));
    return r;
}
__device__ __forceinline__ void unpack2(unsigned long long v, float &lo, float &hi) {
    asm("mov.b64 {%0, %1}, %2;" : "=f"(lo), "=f"(hi) : "l"(v));
}
__device__ __forceinline__ float ex2a(float x) {
    float r; asm("ex2.approx.f32 %0, %1;" : "=f"(r) : "f"(x)); return r;
}

__global__ __launch_bounds__(TPB)
void gat_adj_kernel(const float* __restrict__ x,
                    const float* __restrict__ Wc,
                    const float* __restrict__ Wa,
                    float* __restrict__ out)
{
    __shared__ __align__(16) float buf[1200];           // 16 partial slots x 75 cols
    __shared__ float uu[18];                            // [which*9+i*3+k], /64 folded
    __shared__ unsigned long long ep1[75], ep2[75];     // packed (E,F) per column

    const int n   = blockIdx.x;
    const int tid = threadIdx.x;

    if (tid < 300) {
        // ---- Loader warps: pure x path. 4 LDG.128 at t=0, f32x2 fold, STS.128 ----
        const ulonglong2* xg = reinterpret_cast<const ulonglong2*>(x) + (size_t)n * 1200;
        ulonglong2 xa = xg[tid];
        ulonglong2 xb = xg[tid + 300];
        ulonglong2 xc = xg[tid + 600];
        ulonglong2 xd = xg[tid + 900];
        ulonglong2 s;
        s.x = add2(add2(xa.x, xb.x), add2(xc.x, xd.x));
        s.y = add2(add2(xa.y, xb.y), add2(xc.y, xd.y));
        reinterpret_cast<ulonglong2*>(buf)[tid] = s;   // buf[slot*75+col], col=(4tid+m)%75
    } else if (tid >= 304) {
        // ---- u warps: 18 outputs x 8 lanes x 8 terms, overlapped with x latency ----
        const int idx = tid - 304;                      // 0..143
        const bool on = (idx < 144);                    // always true (TPB=448)
        const int o = idx >> 3;                         // 0..17
        const int p = idx & 7;
        const int which = o / 9;
        const int rem   = o % 9;
        const int i     = rem / 3;
        const int k     = rem % 3;
        const int c0    = p * 8;
        const float* wcb = Wc + i * 192 + k;
        const float4 wa0 = *reinterpret_cast<const float4*>(Wa + which * 64 + c0);
        const float4 wa1 = *reinterpret_cast<const float4*>(Wa + which * 64 + c0 + 4);
        float acc = wcb[(c0 + 0) * 3] * wa0.x + wcb[(c0 + 1) * 3] * wa0.y
                  + wcb[(c0 + 2) * 3] * wa0.z + wcb[(c0 + 3) * 3] * wa0.w
                  + wcb[(c0 + 4) * 3] * wa1.x + wcb[(c0 + 5) * 3] * wa1.y
                  + wcb[(c0 + 6) * 3] * wa1.z + wcb[(c0 + 7) * 3] * wa1.w;
        // warp 9 executes with lanes 16-31 only; warps 10-13 with all lanes.
        const unsigned mask = (tid < 320) ? 0xFFFF0000u : 0xFFFFFFFFu;
        acc += __shfl_xor_sync(mask, acc, 1);
        acc += __shfl_xor_sync(mask, acc, 2);
        acc += __shfl_xor_sync(mask, acc, 4);
        if (p == 0 && on) uu[o] = acc * (1.0f / 64.0f);
    }
    __syncthreads();   // bar 0

    // ---- Phase 2: fold + scores + exps; 3 warps, col = w*27+lane ----
    if (tid < 96) {
        const int w    = tid >> 5;
        const int lane = tid & 31;
        const int col  = w * 27 + lane;
        const bool on  = (lane < 27) && (col < 75);
        const int colc = on ? col : 74;

        float xv = 0.f;
        #pragma unroll
        for (int i = 0; i < 16; i++) xv += buf[i * 75 + colc];

        const int k    = lane % 3;                     // == col%3 when on
        const int base = lane - k;
        const float a0 = __shfl_sync(0xffffffffu, xv, base);
        const float a1 = __shfl_sync(0xffffffffu, xv, base + 1);
        const float a2 = __shfl_sync(0xffffffffu, xv, base + 2);

        const float s1 = a0 * uu[k]     + a1 * uu[3 + k]  + a2 * uu[6 + k];
        const float s2 = a0 * uu[9 + k] + a1 * uu[12 + k] + a2 * uu[15 + k];
        const float L2E  = 1.4426950408889634f;
        const float L2E5 = 0.2f * L2E;
        const float E1 = ex2a(s1 * L2E),  F1 = ex2a(s1 * L2E5);
        const float E2 = ex2a(s2 * L2E),  F2 = ex2a(s2 * L2E5);
        if (on) {
            ep1[col] = pack2(E1, F1);
            ep2[col] = pack2(E2, F2);
        }
    }
    __syncthreads();   // bar 1

    // ---- Phase 3: softmax, 4 threads/row (verified map), MUFU-free hot loop ----
    {
        int row = tid >> 2;
        if (row > 74) row = 74;                 // tid 300..447: safe duplicate work
        const int part = tid & 3;
        const int d  = row % 3;
        const int a3 = row - d;
        const int r0 = d * 25;

        const unsigned long long c0 = ep2[a3];
        const unsigned long long c1 = ep2[a3 + 1];
        const unsigned long long c2 = ep2[a3 + 2];

        const int qs  = (part == 0) ? 0 : part * 6 + 1;   // 0,7,13,19
        const int cnt = (part == 0) ? 7 : 6;

        const int kk0 = (d + qs) % 3;
        unsigned long long ra = (kk0 == 0) ? c0 : ((kk0 == 1) ? c1 : c2);
        unsigned long long rb = (kk0 == 0) ? c1 : ((kk0 == 1) ? c2 : c0);
        unsigned long long rc = (kk0 == 0) ? c2 : ((kk0 == 1) ? c0 : c1);

        float vals[7];
        float sum0 = 0.f, sum1 = 0.f;
        #pragma unroll
        for (int j = 0; j < 7; j++) {
            if (j < cnt) {
                const unsigned long long pr = mul2(ep1[r0 + qs + j], ra);
                float pe, pf;
                unpack2(pr, pe, pf);
                const float vl = fmaxf(pe, pf);   // exp2(leaky(e)) by monotonicity
                vals[j] = vl;
                if (j & 1) sum1 += vl; else sum0 += vl;
                unsigned long long t = ra; ra = rb; rb = rc; rc = t;
            }
        }
        float sum = sum0 + sum1;
        sum += __shfl_xor_sync(0xffffffffu, sum, 1);
        sum += __shfl_xor_sync(0xffffffffu, sum, 2);
        const float inv = __fdividef(1.0f, sum);

        if ((tid >> 2) < 75) {
            float* og = out + (size_t)n * 1875 + row * 25 + qs;
            #pragma unroll
            for (int j = 0; j < 7; j++)
                if (j < cnt) og[j] = vals[j] * inv;
        }
    }
}

extern "C" void kernel_launch(void* const* d_in, const int* in_sizes, int n_in,
                              void* d_out, int out_size)
{
    const float* x  = (const float*)d_in[0];
    const float* Wc = (const float*)d_in[1];
    const float* Wa = (const float*)d_in[2];
    float* out = (float*)d_out;
    gat_adj_kernel<<<256, TPB>>>(x, Wc, Wa, out);
}